// round 11
// baseline (speedup 1.0000x reference)
#include <cuda_runtime.h>
#include <cuda_fp16.h>
#include <cstdint>
#include <cstddef>

#define NT 512
#define NH 128
#define ND 32
#define CS 8
#define NTHR 512
#define NB 64
#define DSTR 34
#define NPOS(hp) (((hp) & 0x38) | (((hp) & 3) << 1) | (((hp) >> 2) & 1))

__device__ float g_deriv[(size_t)NT * 3 * NB * ND];

__global__ void prep_deriv(const float* __restrict__ ts, const float* __restrict__ cd,
                           const float* __restrict__ cc, const float* __restrict__ cb) {
    int b = blockIdx.x, chunk = blockIdx.y;
    int sl = threadIdx.x >> 5, d = threadIdx.x & 31;
    int s = chunk * 16 + sl;
    __shared__ float tsv[NT];
    for (int i = threadIdx.x; i < NT; i += 512) tsv[i] = ts[(size_t)b * NT + i];
    __syncthreads();
    float dt = tsv[1] - tsv[0], t0 = tsv[0];
    for (int i = 0; i < s; ++i) t0 += dt;
    for (int stg = 0; stg < 3; ++stg) {
        float te = (stg == 0) ? t0 : ((stg == 1) ? t0 + 0.5f * dt : t0 + 0.75f * dt);
        int idx = 0;
        #pragma unroll
        for (int stp = 256; stp > 0; stp >>= 1) {
            int c2 = idx + stp;
            if (c2 < NT && tsv[c2] <= te) idx = c2;
        }
        if (idx > NT - 2) idx = NT - 2;
        float fr = te - tsv[idx];
        size_t off = ((size_t)b * (NT - 1) + idx) * ND + d;
        g_deriv[(((size_t)s * 3 + stg) * NB + b) * ND + d] =
            cb[off] + fr * (2.0f * cc[off] + fr * 3.0f * cd[off]);
    }
}

struct __align__(16) SM {
    uint32_t W0f[8 * 8 * 32 * 4];  // 32 KB prebuilt A-frags [w8][ks][lane][4]
    uint32_t W1f[8 * 8 * 32 * 4];  // 32 KB
    uint32_t BtA[8 * 68];
    uint32_t BtB[8 * 68];
    float2   y2[64 * 8];
    float    y_lin[128];
    __half   kh[2][3][128 * 8];
    float    drv[2][3][8 * DSTR];
    float    b0v[128], b1v[128], lwv[128];
    float    a0s[32];
    unsigned long long kbar;
};

__device__ __forceinline__ uint32_t smem_u32(const void* p) {
    uint32_t a;
    asm("{ .reg .u64 t; cvta.to.shared.u64 t, %1; cvt.u32.u64 %0, t; }" : "=r"(a) : "l"(p));
    return a;
}
__device__ __forceinline__ uint32_t mapa_u32(uint32_t addr, uint32_t rank) {
    uint32_t r;
    asm("mapa.shared::cluster.u32 %0, %1, %2;" : "=r"(r) : "r"(addr), "r"(rank));
    return r;
}
__device__ __forceinline__ void st_async64(uint32_t ra, uint64_t v, uint32_t rb) {
    asm volatile("st.async.shared::cluster.mbarrier::complete_tx::bytes.b64 [%0], %1, [%2];"
                 :: "r"(ra), "l"(v), "r"(rb) : "memory");
}
__device__ __forceinline__ void mbar_init(uint32_t mb, uint32_t cnt) {
    asm volatile("mbarrier.init.shared.b64 [%0], %1;" :: "r"(mb), "r"(cnt) : "memory");
}
__device__ __forceinline__ void mbar_expect(uint32_t mb, uint32_t tx) {
    asm volatile("mbarrier.arrive.expect_tx.shared::cta.b64 _, [%0], %1;"
                 :: "r"(mb), "r"(tx) : "memory");
}
__device__ __forceinline__ void mbar_wait(uint32_t mb, uint32_t parity) {
    uint32_t done;
    asm volatile("{\n\t.reg .pred p;\n\t"
                 "mbarrier.try_wait.parity.acquire.cluster.shared::cta.b64 p, [%1], %2;\n\t"
                 "selp.b32 %0, 1, 0, p;\n\t}" : "=r"(done) : "r"(mb), "r"(parity) : "memory");
    if (!done) {
        asm volatile("{\n\t.reg .pred P1;\n\t"
                     "WL_%=:\n\t"
                     "mbarrier.try_wait.parity.acquire.cluster.shared::cta.b64 P1, [%0], %1, 0x989680;\n\t"
                     "@P1 bra.uni WD_%=;\n\t"
                     "bra.uni WL_%=;\n\t"
                     "WD_%=:\n\t}" :: "r"(mb), "r"(parity) : "memory");
    }
}
#define CLUSTER_SYNC() do { \
    asm volatile("barrier.cluster.arrive.aligned;" ::: "memory"); \
    asm volatile("barrier.cluster.wait.aligned;"   ::: "memory"); } while (0)

__device__ __forceinline__ void mma16816(float* c, const uint32_t* a, uint32_t b0, uint32_t b1) {
    asm volatile("mma.sync.aligned.m16n8k16.row.col.f32.f16.f16.f32 "
                 "{%0,%1,%2,%3}, {%4,%5,%6,%7}, {%8,%9}, {%0,%1,%2,%3};"
                 : "+f"(c[0]), "+f"(c[1]), "+f"(c[2]), "+f"(c[3])
                 : "r"(a[0]), "r"(a[1]), "r"(a[2]), "r"(a[3]), "r"(b0), "r"(b1));
}
__device__ __forceinline__ float tanh_fast(float x) {
    float y; asm("tanh.approx.f32 %0, %1;" : "=f"(y) : "f"(x)); return y;
}
__device__ __forceinline__ float sp_f(float x) {
    float e = __expf(-fabsf(x));
    return fmaxf(x, 0.0f) + __logf(1.0f + e);
}
__device__ __forceinline__ uint32_t pack_h2(float a, float b) {
    __half2 h = __floats2half2_rn(a, b);
    return *reinterpret_cast<uint32_t*>(&h);
}
__device__ __forceinline__ float2 h22f(uint32_t u) {
    __half2 h = *reinterpret_cast<__half2*>(&u);
    return __half22float2(h);
}
__device__ __forceinline__ void sth(char* base, int b, int h, float v) {
    *reinterpret_cast<__half*>(base + ((b * 68 + NPOS(h >> 1)) << 2) + ((h & 1) << 1)) =
        __float2half(v);
}

__global__ void __launch_bounds__(NTHR, 1) __cluster_dims__(CS, 1, 1)
cde_kernel(const float* __restrict__ ts, const float* __restrict__ ca,
           const float* __restrict__ iW0, const float* __restrict__ ib0,
           const float* __restrict__ iW1, const float* __restrict__ ib1,
           const float* __restrict__ iW2, const float* __restrict__ ib2,
           const float* __restrict__ fW0, const float* __restrict__ fb0,
           const float* __restrict__ fW1, const float* __restrict__ fb1,
           const float* __restrict__ fW2, const float* __restrict__ fb2,
           const float* __restrict__ lW, const float* __restrict__ lb,
           float* __restrict__ out)
{
    extern __shared__ char smraw[];
    SM* S = reinterpret_cast<SM*>(smraw);
    const int tid = threadIdx.x, wid = tid >> 5, lane = tid & 31;
    const int gid = lane >> 2, tig = lane & 3;
    const int batch = blockIdx.x;
    const int rank = batch & (CS - 1), cbat0 = batch & ~(CS - 1);

    const uint32_t y2_a   = smem_u32(&S->y2[0]);
    const uint32_t kh_a   = smem_u32(&S->kh[0][0][0]);
    const uint32_t kbar_a = smem_u32(&S->kbar);

    if (tid == 0) {
        mbar_init(kbar_a, 1);
        mbar_expect(kbar_a, 4096);
        asm volatile("fence.mbarrier_init.release.cluster;" ::: "memory");
    }

    // prebuilt A-fragment arrays for layer MMAs
    for (int i = tid; i < 2048; i += NTHR) {
        int w8 = i >> 8, ks = (i >> 5) & 7, ln = i & 31;
        int g = ln >> 2, t4 = ln & 3;
        int h0 = w8 * 16 + g, c0 = ks * 16 + 2 * t4;
        const float* r0 = fW0 + (size_t)h0 * NH;
        const float* r1 = fW0 + (size_t)(h0 + 8) * NH;
        uint32_t* dst = S->W0f + i * 4;
        dst[0] = pack_h2(r0[c0], r0[c0 + 1]);
        dst[1] = pack_h2(r1[c0], r1[c0 + 1]);
        dst[2] = pack_h2(r0[c0 + 8], r0[c0 + 9]);
        dst[3] = pack_h2(r1[c0 + 8], r1[c0 + 9]);
        const float* q0 = fW1 + (size_t)h0 * NH;
        const float* q1 = fW1 + (size_t)(h0 + 8) * NH;
        uint32_t* dst1 = S->W1f + i * 4;
        dst1[0] = pack_h2(q0[c0], q0[c0 + 1]);
        dst1[1] = pack_h2(q1[c0], q1[c0 + 1]);
        dst1[2] = pack_h2(q0[c0 + 8], q0[c0 + 9]);
        dst1[3] = pack_h2(q1[c0 + 8], q1[c0 + 9]);
    }
    if (tid < NH) { S->b0v[tid] = fb0[tid]; S->b1v[tid] = fb1[tid]; S->lwv[tid] = lW[tid]; }

    // register-resident W2 frags (h = rank*16 + wid, 32 rows)
    const int rowbase = rank * 512 + wid * 32;
    uint32_t areg[2][8][4];
    float b2v[2][2];
    #pragma unroll
    for (int t = 0; t < 2; ++t) {
        int r0g = rowbase + t * 16 + gid, r1g = r0g + 8;
        b2v[t][0] = fb2[r0g]; b2v[t][1] = fb2[r1g];
        #pragma unroll
        for (int ks = 0; ks < 8; ++ks) {
            int c0 = ks * 16 + 2 * tig;
            const float* w0 = fW2 + (size_t)r0g * NH;
            const float* w1 = fW2 + (size_t)r1g * NH;
            areg[t][ks][0] = pack_h2(w0[c0], w0[c0 + 1]);
            areg[t][ks][1] = pack_h2(w1[c0], w1[c0 + 1]);
            areg[t][ks][2] = pack_h2(w0[c0 + 8], w0[c0 + 9]);
            areg[t][ks][3] = pack_h2(w1[c0 + 8], w1[c0 + 9]);
        }
    }
    __syncthreads();

    // initial MLP (fp32, exact)
    float* sc1 = reinterpret_cast<float*>(S->BtA);
    float* sc2 = reinterpret_cast<float*>(S->BtB);
    if (tid < ND) S->a0s[tid] = ca[(size_t)batch * (NT - 1) * ND + tid];
    __syncthreads();
    if (tid < NH) {
        float a = ib0[tid];
        #pragma unroll
        for (int k = 0; k < ND; ++k) a = fmaf(iW0[tid * ND + k], S->a0s[k], a);
        sc1[tid] = fmaxf(a, 0.0f);
    }
    __syncthreads();
    if (tid < NH) {
        float a = ib1[tid];
        for (int k = 0; k < NH; ++k) a = fmaf(iW1[tid * NH + k], sc1[k], a);
        sc2[tid] = fmaxf(a, 0.0f);
    }
    __syncthreads();
    if (tid < NH) {
        float a = ib2[tid];
        for (int k = 0; k < NH; ++k) a = fmaf(iW2[tid * NH + k], sc2[k], a);
        S->y_lin[tid] = a;
    }
    if (tid < 192) {
        int stgp = tid >> 6, r = tid & 63, b = r >> 3, seg = r & 7;
        float4 v = *(const float4*)&g_deriv[(((size_t)0 * 3 + stgp) * NB + cbat0 + b) * ND + seg * 4];
        float* dp = &S->drv[0][stgp][b * DSTR + seg * 4];
        *(float2*)dp = make_float2(v.x, v.y);
        *(float2*)(dp + 2) = make_float2(v.z, v.w);
    }
    __syncthreads();
    CLUSTER_SYNC();

    if (tid < 64) {   // y0 broadcast
        float2 yv = *(const float2*)&S->y_lin[2 * tid];
        uint64_t pay;
        memcpy(&pay, &yv, 8);
        uint32_t off = y2_a + (uint32_t)((tid * 8 + rank) << 3);
        #pragma unroll
        for (int pr = 0; pr < CS; ++pr)
            st_async64(mapa_u32(off, pr), pay, mapa_u32(kbar_a, pr));
    }

    const float dtv = ts[(size_t)batch * NT + 1] - ts[(size_t)batch * NT];
    const float lbv = lb[0];
    uint32_t kpar = 0;
    const int hidx = rank * 16 + wid;
    const int php = tid >> 2, ppb = (tid & 3) * 2;   // pack mapping (warps 0-7)

    for (int s = 0; s < NT; ++s) {
        const int p = s & 1;
        const float* dbuf = &S->drv[p][0][0];
        #pragma unroll 1
        for (int stg = 0; stg < 3; ++stg) {
            float4 pf;
            const bool dopf = (stg == 0) && (tid >= 320);
            if (dopf) {
                int s1 = (s + 1 < NT) ? s + 1 : NT - 1;
                int r = tid - 320;
                int stgp = r >> 6, rr = r & 63, b = rr >> 3, seg = rr & 7;
                pf = *(const float4*)&g_deriv[(((size_t)s1 * 3 + stgp) * NB + cbat0 + b) * ND + seg * 4];
            }
            mbar_wait(kbar_a, kpar); kpar ^= 1;
            if (tid == 0) mbar_expect(kbar_a, 2048);

            if (wid < 8) {
                // ---- pack (2 batch columns per thread) ----
                {
                    float4 y4 = *(const float4*)&S->y2[php * 8 + ppb];
                    float4 yn;
                    const int pw = NPOS(php);
                    if (stg == 0) {
                        if (s > 0) {
                            const __half* kb = &S->kh[1 - p][0][0];
                            int o0 = php * 16 + ppb, o1 = o0 + 8;
                            float2 k0a = h22f(*(const uint32_t*)&kb[o0]);
                            float2 k0b = h22f(*(const uint32_t*)&kb[o1]);
                            float2 k1a = h22f(*(const uint32_t*)&kb[1024 + o0]);
                            float2 k1b = h22f(*(const uint32_t*)&kb[1024 + o1]);
                            float2 k2a = h22f(*(const uint32_t*)&kb[2048 + o0]);
                            float2 k2b = h22f(*(const uint32_t*)&kb[2048 + o1]);
                            float cx0 = fmaf(4.f/9.f, k2a.x*dtv, fmaf(1.f/3.f, k1a.x*dtv, (2.f/9.f)*(k0a.x*dtv)));
                            float cy0 = fmaf(4.f/9.f, k2b.x*dtv, fmaf(1.f/3.f, k1b.x*dtv, (2.f/9.f)*(k0b.x*dtv)));
                            float cx1 = fmaf(4.f/9.f, k2a.y*dtv, fmaf(1.f/3.f, k1a.y*dtv, (2.f/9.f)*(k0a.y*dtv)));
                            float cy1 = fmaf(4.f/9.f, k2b.y*dtv, fmaf(1.f/3.f, k1b.y*dtv, (2.f/9.f)*(k0b.y*dtv)));
                            yn.x = fmaf(cx0, dtv, y4.x);
                            yn.y = fmaf(cy0, dtv, y4.y);
                            yn.z = fmaf(cx1, dtv, y4.z);
                            yn.w = fmaf(cy1, dtv, y4.w);
                            *(float4*)&S->y2[php * 8 + ppb] = yn;
                            if ((rank >> 1) == (tid & 3)) {
                                float2 yl = (rank & 1) ? make_float2(yn.z, yn.w)
                                                       : make_float2(yn.x, yn.y);
                                *(float2*)&S->y_lin[2 * php] = yl;
                            }
                        } else yn = y4;
                    } else {
                        const __half* kb = &S->kh[p][stg - 1][0];
                        int o0 = php * 16 + ppb;
                        float2 ka = h22f(*(const uint32_t*)&kb[o0]);
                        float2 kbv = h22f(*(const uint32_t*)&kb[o0 + 8]);
                        float cf = (stg == 1) ? 0.5f : 0.75f;
                        yn.x = fmaf(ka.x * dtv, cf, y4.x);
                        yn.y = fmaf(kbv.x * dtv, cf, y4.y);
                        yn.z = fmaf(ka.y * dtv, cf, y4.z);
                        yn.w = fmaf(kbv.y * dtv, cf, y4.w);
                    }
                    S->BtA[ppb * 68 + pw]       = pack_h2(yn.x, yn.y);
                    S->BtA[(ppb + 1) * 68 + pw] = pack_h2(yn.z, yn.w);
                }
                asm volatile("bar.sync 1, 256;" ::: "memory");

                // ---- L1 ----
                float cc[4];
                int h0 = (wid << 4) + gid;
                cc[0] = cc[1] = S->b0v[h0];
                cc[2] = cc[3] = S->b0v[h0 + 8];
                {
                    const uint4* af = (const uint4*)(S->W0f + ((wid * 8) * 32 + lane) * 4);
                    #pragma unroll
                    for (int ks = 0; ks < 8; ++ks) {
                        uint4 a4 = af[ks * 32];
                        uint2 bv = *(const uint2*)&S->BtA[gid * 68 + ks * 8 + tig * 2];
                        mma16816(cc, reinterpret_cast<const uint32_t*>(&a4), bv.x, bv.y);
                    }
                }
                char* bb = reinterpret_cast<char*>(S->BtB);
                sth(bb, 2 * tig,     h0,     sp_f(cc[0]));
                sth(bb, 2 * tig + 1, h0,     sp_f(cc[1]));
                sth(bb, 2 * tig,     h0 + 8, sp_f(cc[2]));
                sth(bb, 2 * tig + 1, h0 + 8, sp_f(cc[3]));
                asm volatile("bar.sync 1, 256;" ::: "memory");

                // ---- L2 ----
                cc[0] = cc[1] = S->b1v[h0];
                cc[2] = cc[3] = S->b1v[h0 + 8];
                {
                    const uint4* af = (const uint4*)(S->W1f + ((wid * 8) * 32 + lane) * 4);
                    #pragma unroll
                    for (int ks = 0; ks < 8; ++ks) {
                        uint4 a4 = af[ks * 32];
                        uint2 bv = *(const uint2*)&S->BtB[gid * 68 + ks * 8 + tig * 2];
                        mma16816(cc, reinterpret_cast<const uint32_t*>(&a4), bv.x, bv.y);
                    }
                }
                char* ba = reinterpret_cast<char*>(S->BtA);
                sth(ba, 2 * tig,     h0,     sp_f(cc[0]));
                sth(ba, 2 * tig + 1, h0,     sp_f(cc[1]));
                sth(ba, 2 * tig,     h0 + 8, sp_f(cc[2]));
                sth(ba, 2 * tig + 1, h0 + 8, sp_f(cc[3]));
            } else if (dopf) {
                int r = tid - 320;
                int stgp = r >> 6, rr = r & 63, b = rr >> 3, seg = rr & 7;
                float* dp = &S->drv[1 - p][stgp][b * DSTR + seg * 4];
                *(float2*)dp = make_float2(pf.x, pf.y);
                *(float2*)(dp + 2) = make_float2(pf.z, pf.w);
            }
            __syncthreads();

            if (wid == 8 && stg == 0 && s > 0) {   // output for step s-1 (y_lin fresh)
                float a = S->y_lin[lane] * S->lwv[lane];
                a = fmaf(S->y_lin[lane + 32], S->lwv[lane + 32], a);
                a = fmaf(S->y_lin[lane + 64], S->lwv[lane + 64], a);
                a = fmaf(S->y_lin[lane + 96], S->lwv[lane + 96], a);
                #pragma unroll
                for (int o = 16; o > 0; o >>= 1) a += __shfl_down_sync(0xffffffffu, a, o);
                if (lane == 0)
                    out[(size_t)batch * NT + s - 1] = 1.0f / (1.0f + expf(-(a + lbv)));
            }

            // ---- L3 + epilogue + fp16 k all-gather ----
            {
                float c0[4] = {0.f, 0.f, 0.f, 0.f};
                float c1[4] = {0.f, 0.f, 0.f, 0.f};
                #pragma unroll
                for (int ks = 0; ks < 8; ++ks) {
                    uint2 bv = *(const uint2*)&S->BtA[gid * 68 + ks * 8 + tig * 2];
                    mma16816(c0, areg[0][ks], bv.x, bv.y);
                    mma16816(c1, areg[1][ks], bv.x, bv.y);
                }
                const float* dvE = dbuf + stg * (CS * DSTR) + (2 * tig) * DSTR;
                const float* dvO = dvE + DSTR;
                float pe, po;
                {
                    float z00 = tanh_fast(c0[0] + b2v[0][0]);
                    float z02 = tanh_fast(c0[2] + b2v[0][1]);
                    float z10 = tanh_fast(c1[0] + b2v[1][0]);
                    float z12 = tanh_fast(c1[2] + b2v[1][1]);
                    pe = z00 * dvE[gid] + z02 * dvE[gid + 8] + z10 * dvE[gid + 16] + z12 * dvE[gid + 24];
                    float z01 = tanh_fast(c0[1] + b2v[0][0]);
                    float z03 = tanh_fast(c0[3] + b2v[0][1]);
                    float z11 = tanh_fast(c1[1] + b2v[1][0]);
                    float z13 = tanh_fast(c1[3] + b2v[1][1]);
                    po = z01 * dvO[gid] + z03 * dvO[gid + 8] + z11 * dvO[gid + 16] + z13 * dvO[gid + 24];
                }
                #pragma unroll
                for (int m = 4; m < 32; m <<= 1) {
                    pe += __shfl_xor_sync(0xffffffffu, pe, m);
                    po += __shfl_xor_sync(0xffffffffu, po, m);
                }
                uint32_t b32h = pack_h2(pe, po);
                uint32_t lo = __shfl_sync(0xffffffffu, b32h, 2 * lane);
                uint32_t hi = __shfl_sync(0xffffffffu, b32h, 2 * lane + 1);
                if (lane < 2) {
                    uint64_t pay = (uint64_t)lo | ((uint64_t)hi << 32);
                    uint32_t boff = kh_a + (uint32_t)((p * 3 + stg) * 2048 + hidx * 16 + lane * 8);
                    #pragma unroll
                    for (int pr = 0; pr < CS; ++pr)
                        st_async64(mapa_u32(boff, pr), pay, mapa_u32(kbar_a, pr));
                }
            }
        }
    }

    // final: wait last k, update own batch, write out[NT-1]
    mbar_wait(kbar_a, kpar);
    if (tid < 64) {
        const __half* kb = &S->kh[1][0][0];
        int o0 = (2 * tid) * 8 + rank, o1 = o0 + 8;
        float2 yv = S->y2[tid * 8 + rank];
        float k0x = __half2float(kb[o0]),        k0y = __half2float(kb[o1]);
        float k1x = __half2float(kb[1024 + o0]), k1y = __half2float(kb[1024 + o1]);
        float k2x = __half2float(kb[2048 + o0]), k2y = __half2float(kb[2048 + o1]);
        float cx = fmaf(4.f/9.f, k2x * dtv, fmaf(1.f/3.f, k1x * dtv, (2.f/9.f) * (k0x * dtv)));
        float cy = fmaf(4.f/9.f, k2y * dtv, fmaf(1.f/3.f, k1y * dtv, (2.f/9.f) * (k0y * dtv)));
        yv.x = fmaf(cx, dtv, yv.x);
        yv.y = fmaf(cy, dtv, yv.y);
        *(float2*)&S->y_lin[2 * tid] = yv;
    }
    __syncthreads();
    if (wid == 8) {
        float a = S->y_lin[lane] * S->lwv[lane];
        a = fmaf(S->y_lin[lane + 32], S->lwv[lane + 32], a);
        a = fmaf(S->y_lin[lane + 64], S->lwv[lane + 64], a);
        a = fmaf(S->y_lin[lane + 96], S->lwv[lane + 96], a);
        #pragma unroll
        for (int o = 16; o > 0; o >>= 1) a += __shfl_down_sync(0xffffffffu, a, o);
        if (lane == 0)
            out[(size_t)batch * NT + NT - 1] = 1.0f / (1.0f + expf(-(a + lbv)));
    }
    CLUSTER_SYNC();
}

extern "C" void kernel_launch(void* const* d_in, const int* in_sizes, int n_in,
                              void* d_out, int out_size) {
    const float* ts  = (const float*)d_in[0];
    const float* cd  = (const float*)d_in[1];
    const float* cc  = (const float*)d_in[2];
    const float* cb  = (const float*)d_in[3];
    const float* ca  = (const float*)d_in[4];
    const float* iW0 = (const float*)d_in[5];
    const float* ib0 = (const float*)d_in[6];
    const float* iW1 = (const float*)d_in[7];
    const float* ib1 = (const float*)d_in[8];
    const float* iW2 = (const float*)d_in[9];
    const float* ib2 = (const float*)d_in[10];
    const float* fW0 = (const float*)d_in[11];
    const float* fb0 = (const float*)d_in[12];
    const float* fW1 = (const float*)d_in[13];
    const float* fb1 = (const float*)d_in[14];
    const float* fW2 = (const float*)d_in[15];
    const float* fb2 = (const float*)d_in[16];
    const float* lW  = (const float*)d_in[17];
    const float* lb  = (const float*)d_in[18];
    float* o = (float*)d_out;

    prep_deriv<<<dim3(NB, NT / 16), 512>>>(ts, cd, cc, cb);
    cudaFuncSetAttribute(cde_kernel, cudaFuncAttributeMaxDynamicSharedMemorySize,
                         (int)sizeof(SM));
    cde_kernel<<<NB, NTHR, sizeof(SM)>>>(ts, ca,
                                         iW0, ib0, iW1, ib1, iW2, ib2,
                                         fW0, fb0, fW1, fb1, fW2, fb2,
                                         lW, lb, o);
}

// round 12
// speedup vs baseline: 1.1789x; 1.1789x over previous
#include <cuda_runtime.h>
#include <cuda_fp16.h>
#include <cstdint>
#include <cstddef>

#define NT 512
#define NH 128
#define ND 32
#define CS 8
#define NTHR 512
#define NB 64
#define DSTR 34

__device__ float g_deriv[(size_t)NT * 3 * NB * ND];

__global__ void prep_deriv(const float* __restrict__ ts, const float* __restrict__ cd,
                           const float* __restrict__ cc, const float* __restrict__ cb) {
    int b = blockIdx.x, chunk = blockIdx.y;
    int sl = threadIdx.x >> 5, d = threadIdx.x & 31;
    int s = chunk * 16 + sl;
    __shared__ float tsv[NT];
    for (int i = threadIdx.x; i < NT; i += 512) tsv[i] = ts[(size_t)b * NT + i];
    __syncthreads();
    float dt = tsv[1] - tsv[0], t0 = tsv[0];
    for (int i = 0; i < s; ++i) t0 += dt;          // exact fp32 carry, matches scan
    for (int stg = 0; stg < 3; ++stg) {
        float te = (stg == 0) ? t0 : ((stg == 1) ? t0 + 0.5f * dt : t0 + 0.75f * dt);
        int idx = 0;
        #pragma unroll
        for (int stp = 256; stp > 0; stp >>= 1) {
            int c2 = idx + stp;
            if (c2 < NT && tsv[c2] <= te) idx = c2;
        }
        if (idx > NT - 2) idx = NT - 2;
        float fr = te - tsv[idx];
        size_t off = ((size_t)b * (NT - 1) + idx) * ND + d;
        g_deriv[(((size_t)s * 3 + stg) * NB + b) * ND + d] =
            cb[off] + fr * (2.0f * cc[off] + fr * 3.0f * cd[off]);
    }
}

struct __align__(16) SM {
    uint32_t W0f[8 * 8 * 32 * 4];  // 32 KB prebuilt A-frags [w8][ks][lane][4]
    uint32_t W1f[8 * 8 * 32 * 4];  // 32 KB
    uint32_t BtA[8 * 68];
    uint32_t BtB[8 * 68];
    float2   y2[64 * 8];           // y state [hpair][batch]
    float    y_lin[128];           // own-batch linear copy
    __half   kh[2][3][128 * 8];    // received k, fp16, [parity][stg][h][batch]
    float    drv[2][3][8 * DSTR];
    float    b0v[128], b1v[128], lwv[128];
    float    a0s[32];
    unsigned long long kbar;
};

__device__ __forceinline__ uint32_t smem_u32(const void* p) {
    uint32_t a;
    asm("{ .reg .u64 t; cvta.to.shared.u64 t, %1; cvt.u32.u64 %0, t; }" : "=r"(a) : "l"(p));
    return a;
}
__device__ __forceinline__ uint32_t mapa_u32(uint32_t addr, uint32_t rank) {
    uint32_t r;
    asm("mapa.shared::cluster.u32 %0, %1, %2;" : "=r"(r) : "r"(addr), "r"(rank));
    return r;
}
__device__ __forceinline__ void st_async64(uint32_t ra, uint64_t v, uint32_t rb) {
    asm volatile("st.async.shared::cluster.mbarrier::complete_tx::bytes.b64 [%0], %1, [%2];"
                 :: "r"(ra), "l"(v), "r"(rb) : "memory");
}
__device__ __forceinline__ void mbar_init(uint32_t mb, uint32_t cnt) {
    asm volatile("mbarrier.init.shared.b64 [%0], %1;" :: "r"(mb), "r"(cnt) : "memory");
}
__device__ __forceinline__ void mbar_expect(uint32_t mb, uint32_t tx) {
    asm volatile("mbarrier.arrive.expect_tx.shared::cta.b64 _, [%0], %1;"
                 :: "r"(mb), "r"(tx) : "memory");
}
__device__ __forceinline__ void mbar_wait(uint32_t mb, uint32_t parity) {
    uint32_t done;
    asm volatile("{\n\t.reg .pred p;\n\t"
                 "mbarrier.try_wait.parity.acquire.cluster.shared::cta.b64 p, [%1], %2;\n\t"
                 "selp.b32 %0, 1, 0, p;\n\t}" : "=r"(done) : "r"(mb), "r"(parity) : "memory");
    if (!done) {
        asm volatile("{\n\t.reg .pred P1;\n\t"
                     "WL_%=:\n\t"
                     "mbarrier.try_wait.parity.acquire.cluster.shared::cta.b64 P1, [%0], %1, 0x989680;\n\t"
                     "@P1 bra.uni WD_%=;\n\t"
                     "bra.uni WL_%=;\n\t"
                     "WD_%=:\n\t}" :: "r"(mb), "r"(parity) : "memory");
    }
}
#define CLUSTER_SYNC() do { \
    asm volatile("barrier.cluster.arrive.aligned;" ::: "memory"); \
    asm volatile("barrier.cluster.wait.aligned;"   ::: "memory"); } while (0)

__device__ __forceinline__ void mma16816(float* c, const uint32_t* a, uint32_t b0, uint32_t b1) {
    asm volatile("mma.sync.aligned.m16n8k16.row.col.f32.f16.f16.f32 "
                 "{%0,%1,%2,%3}, {%4,%5,%6,%7}, {%8,%9}, {%0,%1,%2,%3};"
                 : "+f"(c[0]), "+f"(c[1]), "+f"(c[2]), "+f"(c[3])
                 : "r"(a[0]), "r"(a[1]), "r"(a[2]), "r"(a[3]), "r"(b0), "r"(b1));
}
__device__ __forceinline__ float tanh_fast(float x) {
    float y; asm("tanh.approx.f32 %0, %1;" : "=f"(y) : "f"(x)); return y;
}
__device__ __forceinline__ float sp_f(float x) {
    float e = __expf(-fabsf(x));
    return fmaxf(x, 0.0f) + __logf(1.0f + e);
}
__device__ __forceinline__ uint32_t pack_h2(float a, float b) {
    __half2 h = __floats2half2_rn(a, b);
    return *reinterpret_cast<uint32_t*>(&h);
}
__device__ __forceinline__ void sth(char* base, int b, int h, float v) {
    *reinterpret_cast<__half*>(base + ((b * 68 + (h >> 1)) << 2) + ((h & 1) << 1)) = __float2half(v);
}

__global__ void __launch_bounds__(NTHR, 1) __cluster_dims__(CS, 1, 1)
cde_kernel(const float* __restrict__ ts, const float* __restrict__ ca,
           const float* __restrict__ iW0, const float* __restrict__ ib0,
           const float* __restrict__ iW1, const float* __restrict__ ib1,
           const float* __restrict__ iW2, const float* __restrict__ ib2,
           const float* __restrict__ fW0, const float* __restrict__ fb0,
           const float* __restrict__ fW1, const float* __restrict__ fb1,
           const float* __restrict__ fW2, const float* __restrict__ fb2,
           const float* __restrict__ lW, const float* __restrict__ lb,
           float* __restrict__ out)
{
    extern __shared__ char smraw[];
    SM* S = reinterpret_cast<SM*>(smraw);
    const int tid = threadIdx.x, wid = tid >> 5, lane = tid & 31;
    const int gid = lane >> 2, tig = lane & 3;
    const int batch = blockIdx.x;
    const int rank = batch & (CS - 1), cbat0 = batch & ~(CS - 1);

    const uint32_t y2_a   = smem_u32(&S->y2[0]);
    const uint32_t kh_a   = smem_u32(&S->kh[0][0][0]);
    const uint32_t kbar_a = smem_u32(&S->kbar);

    if (tid == 0) {
        mbar_init(kbar_a, 1);
        mbar_expect(kbar_a, 4096);   // phase 0: y0 broadcast (8 CTAs x 512 B)
        asm volatile("fence.mbarrier_init.release.cluster;" ::: "memory");
    }

    // prebuilt A-fragment arrays for layer MMAs (frag order matches mma usage)
    for (int i = tid; i < 2048; i += NTHR) {
        int w8 = i >> 8, ks = (i >> 5) & 7, ln = i & 31;
        int g = ln >> 2, t4 = ln & 3;
        int h0 = w8 * 16 + g, c0 = ks * 16 + 2 * t4;
        const float* r0 = fW0 + (size_t)h0 * NH;
        const float* r1 = fW0 + (size_t)(h0 + 8) * NH;
        uint32_t* dst = S->W0f + i * 4;
        dst[0] = pack_h2(r0[c0], r0[c0 + 1]);
        dst[1] = pack_h2(r1[c0], r1[c0 + 1]);
        dst[2] = pack_h2(r0[c0 + 8], r0[c0 + 9]);
        dst[3] = pack_h2(r1[c0 + 8], r1[c0 + 9]);
        const float* q0 = fW1 + (size_t)h0 * NH;
        const float* q1 = fW1 + (size_t)(h0 + 8) * NH;
        uint32_t* dst1 = S->W1f + i * 4;
        dst1[0] = pack_h2(q0[c0], q0[c0 + 1]);
        dst1[1] = pack_h2(q1[c0], q1[c0 + 1]);
        dst1[2] = pack_h2(q0[c0 + 8], q0[c0 + 9]);
        dst1[3] = pack_h2(q1[c0 + 8], q1[c0 + 9]);
    }
    if (tid < NH) { S->b0v[tid] = fb0[tid]; S->b1v[tid] = fb1[tid]; S->lwv[tid] = lW[tid]; }

    const int rowbase = rank * 512 + wid * 32;
    uint32_t areg[2][8][4];
    float b2v[2][2];
    #pragma unroll
    for (int t = 0; t < 2; ++t) {
        int r0g = rowbase + t * 16 + gid, r1g = r0g + 8;
        b2v[t][0] = fb2[r0g]; b2v[t][1] = fb2[r1g];
        #pragma unroll
        for (int ks = 0; ks < 8; ++ks) {
            int c0 = ks * 16 + 2 * tig;
            const float* w0 = fW2 + (size_t)r0g * NH;
            const float* w1 = fW2 + (size_t)r1g * NH;
            areg[t][ks][0] = pack_h2(w0[c0], w0[c0 + 1]);
            areg[t][ks][1] = pack_h2(w1[c0], w1[c0 + 1]);
            areg[t][ks][2] = pack_h2(w0[c0 + 8], w0[c0 + 9]);
            areg[t][ks][3] = pack_h2(w1[c0 + 8], w1[c0 + 9]);
        }
    }
    __syncthreads();

    // initial MLP (fp32, exact) -> y0 in y_lin staging
    float* sc1 = reinterpret_cast<float*>(S->BtA);
    float* sc2 = reinterpret_cast<float*>(S->BtB);
    if (tid < ND) S->a0s[tid] = ca[(size_t)batch * (NT - 1) * ND + tid];
    __syncthreads();
    if (tid < NH) {
        float a = ib0[tid];
        #pragma unroll
        for (int k = 0; k < ND; ++k) a = fmaf(iW0[tid * ND + k], S->a0s[k], a);
        sc1[tid] = fmaxf(a, 0.0f);
    }
    __syncthreads();
    if (tid < NH) {
        float a = ib1[tid];
        for (int k = 0; k < NH; ++k) a = fmaf(iW1[tid * NH + k], sc1[k], a);
        sc2[tid] = fmaxf(a, 0.0f);
    }
    __syncthreads();
    if (tid < NH) {
        float a = ib2[tid];
        for (int k = 0; k < NH; ++k) a = fmaf(iW2[tid * NH + k], sc2[k], a);
        S->y_lin[tid] = a;
    }
    if (tid < 192) {   // derivs for s=0
        int stgp = tid >> 6, r = tid & 63, b = r >> 3, seg = r & 7;
        float4 v = *(const float4*)&g_deriv[(((size_t)0 * 3 + stgp) * NB + cbat0 + b) * ND + seg * 4];
        float* dp = &S->drv[0][stgp][b * DSTR + seg * 4];
        *(float2*)dp = make_float2(v.x, v.y);
        *(float2*)(dp + 2) = make_float2(v.z, v.w);
    }
    __syncthreads();
    CLUSTER_SYNC();

    // y0 broadcast: thread t<64 sends own-batch float2 to y2[t][rank] of all peers
    if (tid < 64) {
        float2 yv = *(const float2*)&S->y_lin[2 * tid];
        uint64_t pay;
        memcpy(&pay, &yv, 8);
        uint32_t off = y2_a + (uint32_t)((tid * 8 + rank) << 3);
        #pragma unroll
        for (int pr = 0; pr < CS; ++pr)
            st_async64(mapa_u32(off, pr), pay, mapa_u32(kbar_a, pr));
    }

    const float dtv = ts[(size_t)batch * NT + 1] - ts[(size_t)batch * NT];
    const float lbv = lb[0];
    uint32_t kpar = 0;
    const int pb = tid & 7, hp = tid >> 3;   // pack mapping: batch, h-pair
    const int hidx = rank * 16 + wid;

    for (int s = 0; s < NT; ++s) {
        const int p = s & 1;
        const float* dbuf = &S->drv[p][0][0];
        #pragma unroll 1
        for (int stg = 0; stg < 3; ++stg) {
            float4 pf;
            const bool dopf = (stg == 0) && (tid >= 320);
            if (dopf) {   // prefetch issued BEFORE the wait (latency hidden)
                int s1 = (s + 1 < NT) ? s + 1 : NT - 1;
                int r = tid - 320;
                int stgp = r >> 6, rr = r & 63, b = rr >> 3, seg = rr & 7;
                pf = *(const float4*)&g_deriv[(((size_t)s1 * 3 + stgp) * NB + cbat0 + b) * ND + seg * 4];
            }
            mbar_wait(kbar_a, kpar); kpar ^= 1;
            if (tid == 0) mbar_expect(kbar_a, 2048);

            // ---- pack: yin -> BtA, fold RK update (thread owns (hp, pb)) ----
            {
                float2 yv = S->y2[hp * 8 + pb];
                float2 yn;
                const __half* kb;
                if (stg == 0) {
                    if (s > 0) {
                        kb = &S->kh[1 - p][0][0];
                        int o0 = (2 * hp) * 8 + pb, o1 = o0 + 8;
                        float k0x = __half2float(kb[o0]),        k0y = __half2float(kb[o1]);
                        float k1x = __half2float(kb[1024 + o0]), k1y = __half2float(kb[1024 + o1]);
                        float k2x = __half2float(kb[2048 + o0]), k2y = __half2float(kb[2048 + o1]);
                        float cx = fmaf(4.f/9.f, k2x * dtv, fmaf(1.f/3.f, k1x * dtv, (2.f/9.f) * (k0x * dtv)));
                        float cy = fmaf(4.f/9.f, k2y * dtv, fmaf(1.f/3.f, k1y * dtv, (2.f/9.f) * (k0y * dtv)));
                        yn.x = fmaf(cx, dtv, yv.x);
                        yn.y = fmaf(cy, dtv, yv.y);
                        S->y2[hp * 8 + pb] = yn;
                        if (pb == rank) *(float2*)&S->y_lin[2 * hp] = yn;
                    } else yn = yv;
                } else {
                    kb = &S->kh[p][stg - 1][0];
                    int o0 = (2 * hp) * 8 + pb;
                    float kx = __half2float(kb[o0]), ky = __half2float(kb[o0 + 8]);
                    float cf = (stg == 1) ? 0.5f : 0.75f;
                    yn.x = fmaf(kx * dtv, cf, yv.x);
                    yn.y = fmaf(ky * dtv, cf, yv.y);
                }
                S->BtA[pb * 68 + hp] = pack_h2(yn.x, yn.y);
            }
            __syncthreads();

            if (wid < 8) {
                // ---- L1 ----
                float cc[4];
                int h0 = (wid << 4) + gid;
                cc[0] = cc[1] = S->b0v[h0];
                cc[2] = cc[3] = S->b0v[h0 + 8];
                {
                    const uint4* af = (const uint4*)(S->W0f + ((wid * 8) * 32 + lane) * 4);
                    #pragma unroll
                    for (int ks = 0; ks < 8; ++ks) {
                        uint4 a4 = af[ks * 32];
                        mma16816(cc, reinterpret_cast<const uint32_t*>(&a4),
                                 S->BtA[gid * 68 + ks * 8 + tig], S->BtA[gid * 68 + ks * 8 + tig + 4]);
                    }
                }
                char* bb = reinterpret_cast<char*>(S->BtB);
                sth(bb, 2 * tig,     h0,     sp_f(cc[0]));
                sth(bb, 2 * tig + 1, h0,     sp_f(cc[1]));
                sth(bb, 2 * tig,     h0 + 8, sp_f(cc[2]));
                sth(bb, 2 * tig + 1, h0 + 8, sp_f(cc[3]));
                asm volatile("bar.sync 1, 256;" ::: "memory");
                // ---- L2 ----
                cc[0] = cc[1] = S->b1v[h0];
                cc[2] = cc[3] = S->b1v[h0 + 8];
                {
                    const uint4* af = (const uint4*)(S->W1f + ((wid * 8) * 32 + lane) * 4);
                    #pragma unroll
                    for (int ks = 0; ks < 8; ++ks) {
                        uint4 a4 = af[ks * 32];
                        mma16816(cc, reinterpret_cast<const uint32_t*>(&a4),
                                 S->BtB[gid * 68 + ks * 8 + tig], S->BtB[gid * 68 + ks * 8 + tig + 4]);
                    }
                }
                char* ba = reinterpret_cast<char*>(S->BtA);
                sth(ba, 2 * tig,     h0,     sp_f(cc[0]));
                sth(ba, 2 * tig + 1, h0,     sp_f(cc[1]));
                sth(ba, 2 * tig,     h0 + 8, sp_f(cc[2]));
                sth(ba, 2 * tig + 1, h0 + 8, sp_f(cc[3]));
            } else if (stg == 0) {
                if (wid == 8 && s > 0) {
                    float a = S->y_lin[lane] * S->lwv[lane];
                    a = fmaf(S->y_lin[lane + 32], S->lwv[lane + 32], a);
                    a = fmaf(S->y_lin[lane + 64], S->lwv[lane + 64], a);
                    a = fmaf(S->y_lin[lane + 96], S->lwv[lane + 96], a);
                    #pragma unroll
                    for (int o = 16; o > 0; o >>= 1) a += __shfl_down_sync(0xffffffffu, a, o);
                    if (lane == 0)
                        out[(size_t)batch * NT + s - 1] = 1.0f / (1.0f + expf(-(a + lbv)));
                }
                if (dopf) {
                    int r = tid - 320;
                    int stgp = r >> 6, rr = r & 63, b = rr >> 3, seg = rr & 7;
                    float* dp = &S->drv[1 - p][stgp][b * DSTR + seg * 4];
                    *(float2*)dp = make_float2(pf.x, pf.y);
                    *(float2*)(dp + 2) = make_float2(pf.z, pf.w);
                }
            }
            __syncthreads();

            // ---- L3: W2 HMMA + epilogue + fp16 packed k all-gather ----
            {
                float c0[4] = {0.f, 0.f, 0.f, 0.f};
                float c1[4] = {0.f, 0.f, 0.f, 0.f};
                #pragma unroll
                for (int ks = 0; ks < 8; ++ks) {
                    uint32_t b0 = S->BtA[gid * 68 + ks * 8 + tig];
                    uint32_t b1 = S->BtA[gid * 68 + ks * 8 + tig + 4];
                    mma16816(c0, areg[0][ks], b0, b1);
                    mma16816(c1, areg[1][ks], b0, b1);
                }
                const float* dvE = dbuf + stg * (CS * DSTR) + (2 * tig) * DSTR;
                const float* dvO = dvE + DSTR;
                float pe, po;
                {
                    float z00 = tanh_fast(c0[0] + b2v[0][0]);
                    float z02 = tanh_fast(c0[2] + b2v[0][1]);
                    float z10 = tanh_fast(c1[0] + b2v[1][0]);
                    float z12 = tanh_fast(c1[2] + b2v[1][1]);
                    pe = z00 * dvE[gid] + z02 * dvE[gid + 8] + z10 * dvE[gid + 16] + z12 * dvE[gid + 24];
                    float z01 = tanh_fast(c0[1] + b2v[0][0]);
                    float z03 = tanh_fast(c0[3] + b2v[0][1]);
                    float z11 = tanh_fast(c1[1] + b2v[1][0]);
                    float z13 = tanh_fast(c1[3] + b2v[1][1]);
                    po = z01 * dvO[gid] + z03 * dvO[gid + 8] + z11 * dvO[gid + 16] + z13 * dvO[gid + 24];
                }
                #pragma unroll
                for (int m = 4; m < 32; m <<= 1) {
                    pe += __shfl_xor_sync(0xffffffffu, pe, m);
                    po += __shfl_xor_sync(0xffffffffu, po, m);
                }
                uint32_t b32h = pack_h2(pe, po);             // batches 2*tig, 2*tig+1
                uint32_t lo = __shfl_sync(0xffffffffu, b32h, 2 * lane);
                uint32_t hi = __shfl_sync(0xffffffffu, b32h, 2 * lane + 1);
                if (lane < 2) {
                    uint64_t pay = (uint64_t)lo | ((uint64_t)hi << 32);
                    uint32_t boff = kh_a + (uint32_t)((p * 3 + stg) * 2048 + hidx * 16 + lane * 8);
                    #pragma unroll
                    for (int pr = 0; pr < CS; ++pr)
                        st_async64(mapa_u32(boff, pr), pay, mapa_u32(kbar_a, pr));
                }
            }
        }
    }

    // ---- final: wait last k, update own batch, write out[NT-1] ----
    mbar_wait(kbar_a, kpar);
    if (tid < 64) {
        const __half* kb = &S->kh[1][0][0];   // NT-1 is odd -> p=1
        int o0 = (2 * tid) * 8 + rank, o1 = o0 + 8;
        float2 yv = S->y2[tid * 8 + rank];
        float k0x = __half2float(kb[o0]),        k0y = __half2float(kb[o1]);
        float k1x = __half2float(kb[1024 + o0]), k1y = __half2float(kb[1024 + o1]);
        float k2x = __half2float(kb[2048 + o0]), k2y = __half2float(kb[2048 + o1]);
        float cx = fmaf(4.f/9.f, k2x * dtv, fmaf(1.f/3.f, k1x * dtv, (2.f/9.f) * (k0x * dtv)));
        float cy = fmaf(4.f/9.f, k2y * dtv, fmaf(1.f/3.f, k1y * dtv, (2.f/9.f) * (k0y * dtv)));
        yv.x = fmaf(cx, dtv, yv.x);
        yv.y = fmaf(cy, dtv, yv.y);
        *(float2*)&S->y_lin[2 * tid] = yv;
    }
    __syncthreads();
    if (wid == 8) {
        float a = S->y_lin[lane] * S->lwv[lane];
        a = fmaf(S->y_lin[lane + 32], S->lwv[lane + 32], a);
        a = fmaf(S->y_lin[lane + 64], S->lwv[lane + 64], a);
        a = fmaf(S->y_lin[lane + 96], S->lwv[lane + 96], a);
        #pragma unroll
        for (int o = 16; o > 0; o >>= 1) a += __shfl_down_sync(0xffffffffu, a, o);
        if (lane == 0)
            out[(size_t)batch * NT + NT - 1] = 1.0f / (1.0f + expf(-(a + lbv)));
    }
    CLUSTER_SYNC();
}

extern "C" void kernel_launch(void* const* d_in, const int* in_sizes, int n_in,
                              void* d_out, int out_size) {
    const float* ts  = (const float*)d_in[0];
    const float* cd  = (const float*)d_in[1];
    const float* cc  = (const float*)d_in[2];
    const float* cb  = (const float*)d_in[3];
    const float* ca  = (const float*)d_in[4];
    const float* iW0 = (const float*)d_in[5];
    const float* ib0 = (const float*)d_in[6];
    const float* iW1 = (const float*)d_in[7];
    const float* ib1 = (const float*)d_in[8];
    const float* iW2 = (const float*)d_in[9];
    const float* ib2 = (const float*)d_in[10];
    const float* fW0 = (const float*)d_in[11];
    const float* fb0 = (const float*)d_in[12];
    const float* fW1 = (const float*)d_in[13];
    const float* fb1 = (const float*)d_in[14];
    const float* fW2 = (const float*)d_in[15];
    const float* fb2 = (const float*)d_in[16];
    const float* lW  = (const float*)d_in[17];
    const float* lb  = (const float*)d_in[18];
    float* o = (float*)d_out;

    prep_deriv<<<dim3(NB, NT / 16), 512>>>(ts, cd, cc, cb);
    cudaFuncSetAttribute(cde_kernel, cudaFuncAttributeMaxDynamicSharedMemorySize,
                         (int)sizeof(SM));
    cde_kernel<<<NB, NTHR, sizeof(SM)>>>(ts, ca,
                                         iW0, ib0, iW1, ib1, iW2, ib2,
                                         fW0, fb0, fW1, fb1, fW2, fb2,
                                         lW, lb, o);
}

// round 13
// speedup vs baseline: 1.1839x; 1.0043x over previous
#include <cuda_runtime.h>
#include <cuda_fp16.h>
#include <cstdint>
#include <cstddef>

#define NT 512
#define NH 128
#define ND 32
#define CS 8
#define NTHR 512
#define NB 64

__device__ float g_deriv[(size_t)NT * 3 * NB * ND];

__global__ void prep_deriv(const float* __restrict__ ts, const float* __restrict__ cd,
                           const float* __restrict__ cc, const float* __restrict__ cb) {
    int b = blockIdx.x, chunk = blockIdx.y;
    int sl = threadIdx.x >> 5, d = threadIdx.x & 31;
    int s = chunk * 16 + sl;
    __shared__ float tsv[NT];
    for (int i = threadIdx.x; i < NT; i += 512) tsv[i] = ts[(size_t)b * NT + i];
    __syncthreads();
    float dt = tsv[1] - tsv[0], t0 = tsv[0];
    for (int i = 0; i < s; ++i) t0 += dt;          // exact fp32 carry, matches scan
    for (int stg = 0; stg < 3; ++stg) {
        float te = (stg == 0) ? t0 : ((stg == 1) ? t0 + 0.5f * dt : t0 + 0.75f * dt);
        int idx = 0;
        #pragma unroll
        for (int stp = 256; stp > 0; stp >>= 1) {
            int c2 = idx + stp;
            if (c2 < NT && tsv[c2] <= te) idx = c2;
        }
        if (idx > NT - 2) idx = NT - 2;
        float fr = te - tsv[idx];
        size_t off = ((size_t)b * (NT - 1) + idx) * ND + d;
        g_deriv[(((size_t)s * 3 + stg) * NB + b) * ND + d] =
            cb[off] + fr * (2.0f * cc[off] + fr * 3.0f * cd[off]);
    }
}

struct __align__(16) SM {
    uint32_t W0f[8 * 8 * 32 * 4];  // 32 KB prebuilt A-frags
    uint32_t W1f[8 * 8 * 32 * 4];  // 32 KB
    uint32_t BtA[8 * 68];
    uint32_t BtB[8 * 68];
    float2   y2[64 * 8];           // y state [hpair][batch]
    float    y_lin[128];           // own-batch linear copy
    __half   kh[2][3][128 * 8];    // received k, fp16, [parity][stg][h][batch]
    uint32_t drvh[2][3][4 * 40];   // packed deriv half2 (dE,dO) [parity][stg][bp*40 + d]
    float    b0v[128], b1v[128], lwv[128];
    float    a0s[32];
    unsigned long long kbar;
};

__device__ __forceinline__ uint32_t smem_u32(const void* p) {
    uint32_t a;
    asm("{ .reg .u64 t; cvta.to.shared.u64 t, %1; cvt.u32.u64 %0, t; }" : "=r"(a) : "l"(p));
    return a;
}
__device__ __forceinline__ uint32_t mapa_u32(uint32_t addr, uint32_t rank) {
    uint32_t r;
    asm("mapa.shared::cluster.u32 %0, %1, %2;" : "=r"(r) : "r"(addr), "r"(rank));
    return r;
}
__device__ __forceinline__ void st_async64(uint32_t ra, uint64_t v, uint32_t rb) {
    asm volatile("st.async.shared::cluster.mbarrier::complete_tx::bytes.b64 [%0], %1, [%2];"
                 :: "r"(ra), "l"(v), "r"(rb) : "memory");
}
__device__ __forceinline__ void mbar_init(uint32_t mb, uint32_t cnt) {
    asm volatile("mbarrier.init.shared.b64 [%0], %1;" :: "r"(mb), "r"(cnt) : "memory");
}
__device__ __forceinline__ void mbar_expect(uint32_t mb, uint32_t tx) {
    asm volatile("mbarrier.arrive.expect_tx.shared::cta.b64 _, [%0], %1;"
                 :: "r"(mb), "r"(tx) : "memory");
}
__device__ __forceinline__ void mbar_wait(uint32_t mb, uint32_t parity) {
    uint32_t done;
    asm volatile("{\n\t.reg .pred p;\n\t"
                 "mbarrier.try_wait.parity.acquire.cluster.shared::cta.b64 p, [%1], %2;\n\t"
                 "selp.b32 %0, 1, 0, p;\n\t}" : "=r"(done) : "r"(mb), "r"(parity) : "memory");
    if (!done) {
        asm volatile("{\n\t.reg .pred P1;\n\t"
                     "WL_%=:\n\t"
                     "mbarrier.try_wait.parity.acquire.cluster.shared::cta.b64 P1, [%0], %1, 0x989680;\n\t"
                     "@P1 bra.uni WD_%=;\n\t"
                     "bra.uni WL_%=;\n\t"
                     "WD_%=:\n\t}" :: "r"(mb), "r"(parity) : "memory");
    }
}
#define CLUSTER_SYNC() do { \
    asm volatile("barrier.cluster.arrive.aligned;" ::: "memory"); \
    asm volatile("barrier.cluster.wait.aligned;"   ::: "memory"); } while (0)

__device__ __forceinline__ void mma16816(float* c, const uint32_t* a, uint32_t b0, uint32_t b1) {
    asm volatile("mma.sync.aligned.m16n8k16.row.col.f32.f16.f16.f32 "
                 "{%0,%1,%2,%3}, {%4,%5,%6,%7}, {%8,%9}, {%0,%1,%2,%3};"
                 : "+f"(c[0]), "+f"(c[1]), "+f"(c[2]), "+f"(c[3])
                 : "r"(a[0]), "r"(a[1]), "r"(a[2]), "r"(a[3]), "r"(b0), "r"(b1));
}
__device__ __forceinline__ uint32_t tanh2(uint32_t x) {
    uint32_t y; asm("tanh.approx.f16x2 %0, %1;" : "=r"(y) : "r"(x)); return y;
}
__device__ __forceinline__ float sp_f(float x) {
    float e = __expf(-fabsf(x));
    return fmaxf(x, 0.0f) + __logf(1.0f + e);
}
__device__ __forceinline__ uint32_t pack_h2(float a, float b) {
    __half2 h = __floats2half2_rn(a, b);
    return *reinterpret_cast<uint32_t*>(&h);
}
__device__ __forceinline__ uint32_t hfma2u(uint32_t a, uint32_t b, uint32_t c) {
    __half2 r = __hfma2(*reinterpret_cast<__half2*>(&a), *reinterpret_cast<__half2*>(&b),
                        *reinterpret_cast<__half2*>(&c));
    return *reinterpret_cast<uint32_t*>(&r);
}
__device__ __forceinline__ uint32_t hmul2u(uint32_t a, uint32_t b) {
    __half2 r = __hmul2(*reinterpret_cast<__half2*>(&a), *reinterpret_cast<__half2*>(&b));
    return *reinterpret_cast<uint32_t*>(&r);
}
__device__ __forceinline__ uint32_t hadd2u(uint32_t a, uint32_t b) {
    __half2 r = __hadd2(*reinterpret_cast<__half2*>(&a), *reinterpret_cast<__half2*>(&b));
    return *reinterpret_cast<uint32_t*>(&r);
}
__device__ __forceinline__ void sth(char* base, int b, int h, float v) {
    *reinterpret_cast<__half*>(base + ((b * 68 + (h >> 1)) << 2) + ((h & 1) << 1)) = __float2half(v);
}

__global__ void __launch_bounds__(NTHR, 1) __cluster_dims__(CS, 1, 1)
cde_kernel(const float* __restrict__ ts, const float* __restrict__ ca,
           const float* __restrict__ iW0, const float* __restrict__ ib0,
           const float* __restrict__ iW1, const float* __restrict__ ib1,
           const float* __restrict__ iW2, const float* __restrict__ ib2,
           const float* __restrict__ fW0, const float* __restrict__ fb0,
           const float* __restrict__ fW1, const float* __restrict__ fb1,
           const float* __restrict__ fW2, const float* __restrict__ fb2,
           const float* __restrict__ lW, const float* __restrict__ lb,
           float* __restrict__ out)
{
    extern __shared__ char smraw[];
    SM* S = reinterpret_cast<SM*>(smraw);
    const int tid = threadIdx.x, wid = tid >> 5, lane = tid & 31;
    const int gid = lane >> 2, tig = lane & 3;
    const int batch = blockIdx.x;
    const int rank = batch & (CS - 1), cbat0 = batch & ~(CS - 1);

    const uint32_t y2_a   = smem_u32(&S->y2[0]);
    const uint32_t kh_a   = smem_u32(&S->kh[0][0][0]);
    const uint32_t kbar_a = smem_u32(&S->kbar);
    const uint32_t kdelta = kbar_a - kh_a;   // same-CTA address delta (mapa-affine)

    if (tid == 0) {
        mbar_init(kbar_a, 1);
        mbar_expect(kbar_a, 4096);
        asm volatile("fence.mbarrier_init.release.cluster;" ::: "memory");
    }

    for (int i = tid; i < 2048; i += NTHR) {
        int w8 = i >> 8, ks = (i >> 5) & 7, ln = i & 31;
        int g = ln >> 2, t4 = ln & 3;
        int h0 = w8 * 16 + g, c0 = ks * 16 + 2 * t4;
        const float* r0 = fW0 + (size_t)h0 * NH;
        const float* r1 = fW0 + (size_t)(h0 + 8) * NH;
        uint32_t* dst = S->W0f + i * 4;
        dst[0] = pack_h2(r0[c0], r0[c0 + 1]);
        dst[1] = pack_h2(r1[c0], r1[c0 + 1]);
        dst[2] = pack_h2(r0[c0 + 8], r0[c0 + 9]);
        dst[3] = pack_h2(r1[c0 + 8], r1[c0 + 9]);
        const float* q0 = fW1 + (size_t)h0 * NH;
        const float* q1 = fW1 + (size_t)(h0 + 8) * NH;
        uint32_t* dst1 = S->W1f + i * 4;
        dst1[0] = pack_h2(q0[c0], q0[c0 + 1]);
        dst1[1] = pack_h2(q1[c0], q1[c0 + 1]);
        dst1[2] = pack_h2(q0[c0 + 8], q0[c0 + 9]);
        dst1[3] = pack_h2(q1[c0 + 8], q1[c0 + 9]);
    }
    if (tid < NH) { S->b0v[tid] = fb0[tid]; S->b1v[tid] = fb1[tid]; S->lwv[tid] = lW[tid]; }

    const int rowbase = rank * 512 + wid * 32;
    uint32_t areg[2][8][4];
    float b2v[2][2];
    #pragma unroll
    for (int t = 0; t < 2; ++t) {
        int r0g = rowbase + t * 16 + gid, r1g = r0g + 8;
        b2v[t][0] = fb2[r0g]; b2v[t][1] = fb2[r1g];
        #pragma unroll
        for (int ks = 0; ks < 8; ++ks) {
            int c0 = ks * 16 + 2 * tig;
            const float* w0 = fW2 + (size_t)r0g * NH;
            const float* w1 = fW2 + (size_t)r1g * NH;
            areg[t][ks][0] = pack_h2(w0[c0], w0[c0 + 1]);
            areg[t][ks][1] = pack_h2(w1[c0], w1[c0 + 1]);
            areg[t][ks][2] = pack_h2(w0[c0 + 8], w0[c0 + 9]);
            areg[t][ks][3] = pack_h2(w1[c0 + 8], w1[c0 + 9]);
        }
    }
    __syncthreads();

    // initial MLP (fp32, exact)
    float* sc1 = reinterpret_cast<float*>(S->BtA);
    float* sc2 = reinterpret_cast<float*>(S->BtB);
    if (tid < ND) S->a0s[tid] = ca[(size_t)batch * (NT - 1) * ND + tid];
    __syncthreads();
    if (tid < NH) {
        float a = ib0[tid];
        #pragma unroll
        for (int k = 0; k < ND; ++k) a = fmaf(iW0[tid * ND + k], S->a0s[k], a);
        sc1[tid] = fmaxf(a, 0.0f);
    }
    __syncthreads();
    if (tid < NH) {
        float a = ib1[tid];
        for (int k = 0; k < NH; ++k) a = fmaf(iW1[tid * NH + k], sc1[k], a);
        sc2[tid] = fmaxf(a, 0.0f);
    }
    __syncthreads();
    if (tid < NH) {
        float a = ib2[tid];
        for (int k = 0; k < NH; ++k) a = fmaf(iW2[tid * NH + k], sc2[k], a);
        S->y_lin[tid] = a;
    }
    // packed derivs for s=0
    if (tid < 96) {
        int stgp = tid >> 5, rr = tid & 31, bp = rr >> 3, seg = rr & 7;
        const float4 vE = *(const float4*)&g_deriv[(((size_t)0 * 3 + stgp) * NB + cbat0 + 2 * bp) * ND + seg * 4];
        const float4 vO = *(const float4*)&g_deriv[(((size_t)0 * 3 + stgp) * NB + cbat0 + 2 * bp + 1) * ND + seg * 4];
        uint4 u;
        u.x = pack_h2(vE.x, vO.x); u.y = pack_h2(vE.y, vO.y);
        u.z = pack_h2(vE.z, vO.z); u.w = pack_h2(vE.w, vO.w);
        *(uint4*)&S->drvh[0][stgp][bp * 40 + seg * 4] = u;
    }
    __syncthreads();
    CLUSTER_SYNC();

    if (tid < 64) {   // y0 broadcast
        float2 yv = *(const float2*)&S->y_lin[2 * tid];
        uint64_t pay;
        memcpy(&pay, &yv, 8);
        uint32_t off = y2_a + (uint32_t)((tid * 8 + rank) << 3);
        #pragma unroll
        for (int pr = 0; pr < CS; ++pr)
            st_async64(mapa_u32(off, pr), pay, mapa_u32(kbar_a, pr));
    }

    const float dtv = ts[(size_t)batch * NT + 1] - ts[(size_t)batch * NT];
    const float lbv = lb[0];
    uint32_t kpar = 0;
    const int pb = tid & 7, hp = tid >> 3;
    const int hidx = rank * 16 + wid;

    for (int s = 0; s < NT; ++s) {
        const int p = s & 1;
        #pragma unroll 1
        for (int stg = 0; stg < 3; ++stg) {
            float4 pfE, pfO;
            const bool dopf = (stg == 0) && (tid >= 320) && (tid < 416);
            if (dopf) {   // prefetch issued BEFORE the wait
                int s1 = (s + 1 < NT) ? s + 1 : NT - 1;
                int r = tid - 320;
                int stgp = r >> 5, rr = r & 31, bp = rr >> 3, seg = rr & 7;
                pfE = *(const float4*)&g_deriv[(((size_t)s1 * 3 + stgp) * NB + cbat0 + 2 * bp) * ND + seg * 4];
                pfO = *(const float4*)&g_deriv[(((size_t)s1 * 3 + stgp) * NB + cbat0 + 2 * bp + 1) * ND + seg * 4];
            }
            mbar_wait(kbar_a, kpar); kpar ^= 1;
            if (tid == 0) mbar_expect(kbar_a, 2048);

            // ---- pack: yin -> BtA, fold RK update ----
            {
                float2 yv = S->y2[hp * 8 + pb];
                float2 yn;
                const __half* kb;
                if (stg == 0) {
                    if (s > 0) {
                        kb = &S->kh[1 - p][0][0];
                        int o0 = (2 * hp) * 8 + pb, o1 = o0 + 8;
                        float k0x = __half2float(kb[o0]),        k0y = __half2float(kb[o1]);
                        float k1x = __half2float(kb[1024 + o0]), k1y = __half2float(kb[1024 + o1]);
                        float k2x = __half2float(kb[2048 + o0]), k2y = __half2float(kb[2048 + o1]);
                        float cx = fmaf(4.f/9.f, k2x * dtv, fmaf(1.f/3.f, k1x * dtv, (2.f/9.f) * (k0x * dtv)));
                        float cy = fmaf(4.f/9.f, k2y * dtv, fmaf(1.f/3.f, k1y * dtv, (2.f/9.f) * (k0y * dtv)));
                        yn.x = fmaf(cx, dtv, yv.x);
                        yn.y = fmaf(cy, dtv, yv.y);
                        S->y2[hp * 8 + pb] = yn;
                        if (pb == rank) *(float2*)&S->y_lin[2 * hp] = yn;
                    } else yn = yv;
                } else {
                    kb = &S->kh[p][stg - 1][0];
                    int o0 = (2 * hp) * 8 + pb;
                    float kx = __half2float(kb[o0]), ky = __half2float(kb[o0 + 8]);
                    float cf = (stg == 1) ? 0.5f : 0.75f;
                    yn.x = fmaf(kx * dtv, cf, yv.x);
                    yn.y = fmaf(ky * dtv, cf, yv.y);
                }
                S->BtA[pb * 68 + hp] = pack_h2(yn.x, yn.y);
            }
            __syncthreads();

            if (wid < 8) {
                // ---- L1 ----
                float cc[4];
                int h0 = (wid << 4) + gid;
                cc[0] = cc[1] = S->b0v[h0];
                cc[2] = cc[3] = S->b0v[h0 + 8];
                {
                    const uint4* af = (const uint4*)(S->W0f + ((wid * 8) * 32 + lane) * 4);
                    #pragma unroll
                    for (int ks = 0; ks < 8; ++ks) {
                        uint4 a4 = af[ks * 32];
                        mma16816(cc, reinterpret_cast<const uint32_t*>(&a4),
                                 S->BtA[gid * 68 + ks * 8 + tig], S->BtA[gid * 68 + ks * 8 + tig + 4]);
                    }
                }
                char* bb = reinterpret_cast<char*>(S->BtB);
                sth(bb, 2 * tig,     h0,     sp_f(cc[0]));
                sth(bb, 2 * tig + 1, h0,     sp_f(cc[1]));
                sth(bb, 2 * tig,     h0 + 8, sp_f(cc[2]));
                sth(bb, 2 * tig + 1, h0 + 8, sp_f(cc[3]));
                asm volatile("bar.sync 1, 256;" ::: "memory");
                // ---- L2 ----
                cc[0] = cc[1] = S->b1v[h0];
                cc[2] = cc[3] = S->b1v[h0 + 8];
                {
                    const uint4* af = (const uint4*)(S->W1f + ((wid * 8) * 32 + lane) * 4);
                    #pragma unroll
                    for (int ks = 0; ks < 8; ++ks) {
                        uint4 a4 = af[ks * 32];
                        mma16816(cc, reinterpret_cast<const uint32_t*>(&a4),
                                 S->BtB[gid * 68 + ks * 8 + tig], S->BtB[gid * 68 + ks * 8 + tig + 4]);
                    }
                }
                char* ba = reinterpret_cast<char*>(S->BtA);
                sth(ba, 2 * tig,     h0,     sp_f(cc[0]));
                sth(ba, 2 * tig + 1, h0,     sp_f(cc[1]));
                sth(ba, 2 * tig,     h0 + 8, sp_f(cc[2]));
                sth(ba, 2 * tig + 1, h0 + 8, sp_f(cc[3]));
            } else if (stg == 0) {
                if (wid == 8 && s > 0) {
                    float a = S->y_lin[lane] * S->lwv[lane];
                    a = fmaf(S->y_lin[lane + 32], S->lwv[lane + 32], a);
                    a = fmaf(S->y_lin[lane + 64], S->lwv[lane + 64], a);
                    a = fmaf(S->y_lin[lane + 96], S->lwv[lane + 96], a);
                    #pragma unroll
                    for (int o = 16; o > 0; o >>= 1) a += __shfl_down_sync(0xffffffffu, a, o);
                    if (lane == 0)
                        out[(size_t)batch * NT + s - 1] = 1.0f / (1.0f + expf(-(a + lbv)));
                }
                if (dopf) {
                    int r = tid - 320;
                    int stgp = r >> 5, rr = r & 31, bp = rr >> 3, seg = rr & 7;
                    uint4 u;
                    u.x = pack_h2(pfE.x, pfO.x); u.y = pack_h2(pfE.y, pfO.y);
                    u.z = pack_h2(pfE.z, pfO.z); u.w = pack_h2(pfE.w, pfO.w);
                    *(uint4*)&S->drvh[1 - p][stgp][bp * 40 + seg * 4] = u;
                }
            }
            __syncthreads();

            // ---- L3: W2 HMMA + f16x2 epilogue + k all-gather ----
            {
                float c0[4] = {0.f, 0.f, 0.f, 0.f};
                float c1[4] = {0.f, 0.f, 0.f, 0.f};
                #pragma unroll
                for (int ks = 0; ks < 8; ++ks) {
                    uint32_t b0 = S->BtA[gid * 68 + ks * 8 + tig];
                    uint32_t b1 = S->BtA[gid * 68 + ks * 8 + tig + 4];
                    mma16816(c0, areg[0][ks], b0, b1);
                    mma16816(c1, areg[1][ks], b0, b1);
                }
                // z pairs (even,odd batch) -> tanh.f16x2
                uint32_t z0 = tanh2(pack_h2(c0[0] + b2v[0][0], c0[1] + b2v[0][0]));
                uint32_t z1 = tanh2(pack_h2(c0[2] + b2v[0][1], c0[3] + b2v[0][1]));
                uint32_t z2 = tanh2(pack_h2(c1[0] + b2v[1][0], c1[1] + b2v[1][0]));
                uint32_t z3 = tanh2(pack_h2(c1[2] + b2v[1][1], c1[3] + b2v[1][1]));
                // packed deriv (dE,dO) for this (tig, d-rows)
                const uint32_t* dv = &S->drvh[p][stg][tig * 40];
                uint32_t a2 = hmul2u(z0, dv[gid]);
                a2 = hfma2u(z1, dv[gid + 8],  a2);
                a2 = hfma2u(z2, dv[gid + 16], a2);
                a2 = hfma2u(z3, dv[gid + 24], a2);
                #pragma unroll
                for (int m = 4; m < 32; m <<= 1)
                    a2 = hadd2u(a2, __shfl_xor_sync(0xffffffffu, a2, m));
                uint32_t lo = __shfl_sync(0xffffffffu, a2, 2 * lane);
                uint32_t hi = __shfl_sync(0xffffffffu, a2, 2 * lane + 1);
                if (lane < 2) {
                    uint64_t pay = (uint64_t)lo | ((uint64_t)hi << 32);
                    uint32_t boff = kh_a + (uint32_t)((p * 3 + stg) * 2048 + hidx * 16 + lane * 8);
                    uint32_t bdelta = kdelta - (boff - kh_a);
                    #pragma unroll
                    for (int pr = 0; pr < CS; ++pr) {
                        uint32_t dst = mapa_u32(boff, pr);
                        st_async64(dst, pay, dst + bdelta);
                    }
                }
            }
        }
    }

    // final: wait last k, update own batch, write out[NT-1]
    mbar_wait(kbar_a, kpar);
    if (tid < 64) {
        const __half* kb = &S->kh[1][0][0];
        int o0 = (2 * tid) * 8 + rank, o1 = o0 + 8;
        float2 yv = S->y2[tid * 8 + rank];
        float k0x = __half2float(kb[o0]),        k0y = __half2float(kb[o1]);
        float k1x = __half2float(kb[1024 + o0]), k1y = __half2float(kb[1024 + o1]);
        float k2x = __half2float(kb[2048 + o0]), k2y = __half2float(kb[2048 + o1]);
        float cx = fmaf(4.f/9.f, k2x * dtv, fmaf(1.f/3.f, k1x * dtv, (2.f/9.f) * (k0x * dtv)));
        float cy = fmaf(4.f/9.f, k2y * dtv, fmaf(1.f/3.f, k1y * dtv, (2.f/9.f) * (k0y * dtv)));
        yv.x = fmaf(cx, dtv, yv.x);
        yv.y = fmaf(cy, dtv, yv.y);
        *(float2*)&S->y_lin[2 * tid] = yv;
    }
    __syncthreads();
    if (wid == 8) {
        float a = S->y_lin[lane] * S->lwv[lane];
        a = fmaf(S->y_lin[lane + 32], S->lwv[lane + 32], a);
        a = fmaf(S->y_lin[lane + 64], S->lwv[lane + 64], a);
        a = fmaf(S->y_lin[lane + 96], S->lwv[lane + 96], a);
        #pragma unroll
        for (int o = 16; o > 0; o >>= 1) a += __shfl_down_sync(0xffffffffu, a, o);
        if (lane == 0)
            out[(size_t)batch * NT + NT - 1] = 1.0f / (1.0f + expf(-(a + lbv)));
    }
    CLUSTER_SYNC();
}

extern "C" void kernel_launch(void* const* d_in, const int* in_sizes, int n_in,
                              void* d_out, int out_size) {
    const float* ts  = (const float*)d_in[0];
    const float* cd  = (const float*)d_in[1];
    const float* cc  = (const float*)d_in[2];
    const float* cb  = (const float*)d_in[3];
    const float* ca  = (const float*)d_in[4];
    const float* iW0 = (const float*)d_in[5];
    const float* ib0 = (const float*)d_in[6];
    const float* iW1 = (const float*)d_in[7];
    const float* ib1 = (const float*)d_in[8];
    const float* iW2 = (const float*)d_in[9];
    const float* ib2 = (const float*)d_in[10];
    const float* fW0 = (const float*)d_in[11];
    const float* fb0 = (const float*)d_in[12];
    const float* fW1 = (const float*)d_in[13];
    const float* fb1 = (const float*)d_in[14];
    const float* fW2 = (const float*)d_in[15];
    const float* fb2 = (const float*)d_in[16];
    const float* lW  = (const float*)d_in[17];
    const float* lb  = (const float*)d_in[18];
    float* o = (float*)d_out;

    prep_deriv<<<dim3(NB, NT / 16), 512>>>(ts, cd, cc, cb);
    cudaFuncSetAttribute(cde_kernel, cudaFuncAttributeMaxDynamicSharedMemorySize,
                         (int)sizeof(SM));
    cde_kernel<<<NB, NTHR, sizeof(SM)>>>(ts, ca,
                                         iW0, ib0, iW1, ib1, iW2, ib2,
                                         fW0, fb0, fW1, fb1, fW2, fb2,
                                         lW, lb, o);
}